// round 4
// baseline (speedup 1.0000x reference)
#include <cuda_runtime.h>
#include <math.h>

typedef unsigned long long ull;

#define T_STEPS 512
#define BATCH   64
#define INP     1024
#define HID     1024
#define GATES   4096
#define NBLK    128     // persistent blocks (1/SM, co-resident on 148 SMs)
#define NTHR    256

// Scratch (static device arrays — no allocation APIs allowed)
__device__ __align__(16) float g_G[(size_t)T_STEPS * BATCH * GATES];   // 512 MB
__device__ ull       g_bar_gen;   // grid barrier generation (monotonic)
__device__ unsigned  g_bar_cnt;   // grid barrier arrive counter

// ---- packed fp32x2 helpers (Blackwell FFMA2: 2 fp32 FMA per instr, bit-exact) ----
__device__ __forceinline__ ull pk2(float x, float y) {
    ull r; asm("mov.b64 %0, {%1, %2};" : "=l"(r) : "f"(x), "f"(y)); return r;
}
__device__ __forceinline__ ull dup2(float x) {
    ull r; asm("mov.b64 %0, {%1, %1};" : "=l"(r) : "f"(x)); return r;
}
__device__ __forceinline__ void fma2(ull& d, ull a, ull b) {
    asm("fma.rn.f32x2 %0, %1, %2, %0;" : "+l"(d) : "l"(a), "l"(b));
}
__device__ __forceinline__ float2 up2(ull v) {
    float2 f; asm("mov.b64 {%0, %1}, %2;" : "=f"(f.x), "=f"(f.y) : "l"(v)); return f;
}
__device__ __forceinline__ float sigf(float v) { return 1.0f / (1.0f + expf(-v)); }

// ---------------------------------------------------------------------------
// Kernel 1: G = X @ W_ih^T + (b_ih + b_hh)
// M = 32768, N = 4096, K = 1024. 128x128 tile, BK=8, 256 thr, 8x8/thread (FFMA2).
// ---------------------------------------------------------------------------
__global__ __launch_bounds__(256) void input_gemm_kernel(
    const float* __restrict__ X,
    const float* __restrict__ W,
    const float* __restrict__ b_ih,
    const float* __restrict__ b_hh)
{
    __shared__ __align__(16) float As[8][128];
    __shared__ __align__(16) float Bs[8][128];

    const int tid = threadIdx.x;
    const int n0  = blockIdx.x * 128;
    const int m0  = blockIdx.y * 128;
    const int tx  = tid & 15;
    const int ty  = tid >> 4;
    const int lrow = tid >> 1;
    const int lk4  = (tid & 1) * 4;

    ull acc2[8][4];
#pragma unroll
    for (int i = 0; i < 8; i++)
#pragma unroll
        for (int jp = 0; jp < 4; jp++) acc2[i][jp] = 0ULL;

    const float* Arow = X + (size_t)(m0 + lrow) * INP + lk4;
    const float* Brow = W + (size_t)(n0 + lrow) * INP + lk4;

    for (int k0 = 0; k0 < INP; k0 += 8) {
        float4 av = *reinterpret_cast<const float4*>(Arow + k0);
        float4 bv = *reinterpret_cast<const float4*>(Brow + k0);
        __syncthreads();
        As[lk4 + 0][lrow] = av.x; As[lk4 + 1][lrow] = av.y;
        As[lk4 + 2][lrow] = av.z; As[lk4 + 3][lrow] = av.w;
        Bs[lk4 + 0][lrow] = bv.x; Bs[lk4 + 1][lrow] = bv.y;
        Bs[lk4 + 2][lrow] = bv.z; Bs[lk4 + 3][lrow] = bv.w;
        __syncthreads();

#pragma unroll
        for (int kk = 0; kk < 8; kk++) {
            float4 a0 = *reinterpret_cast<const float4*>(&As[kk][ty * 8]);
            float4 a1 = *reinterpret_cast<const float4*>(&As[kk][ty * 8 + 4]);
            float4 b0 = *reinterpret_cast<const float4*>(&Bs[kk][tx * 8]);
            float4 b1 = *reinterpret_cast<const float4*>(&Bs[kk][tx * 8 + 4]);
            ull B4[4] = {pk2(b0.x, b0.y), pk2(b0.z, b0.w),
                         pk2(b1.x, b1.y), pk2(b1.z, b1.w)};
            float a[8] = {a0.x, a0.y, a0.z, a0.w, a1.x, a1.y, a1.z, a1.w};
#pragma unroll
            for (int i = 0; i < 8; i++) {
                ull ad = dup2(a[i]);
#pragma unroll
                for (int jp = 0; jp < 4; jp++) fma2(acc2[i][jp], ad, B4[jp]);
            }
        }
    }

    float bias[8];
#pragma unroll
    for (int j = 0; j < 8; j++) {
        int n = n0 + tx * 8 + j;
        bias[j] = b_ih[n] + b_hh[n];
    }

#pragma unroll
    for (int i = 0; i < 8; i++) {
        size_t row = (size_t)(m0 + ty * 8 + i);
        float* dst = &g_G[row * GATES + n0 + tx * 8];
#pragma unroll
        for (int jp = 0; jp < 4; jp++) {
            float2 v = up2(acc2[i][jp]);
            dst[2 * jp]     = v.x + bias[2 * jp];
            dst[2 * jp + 1] = v.y + bias[2 * jp + 1];
        }
    }
}

// ---------------------------------------------------------------------------
// Kernel 2: persistent reverse-LSTM recurrence. One launch, 512 steps,
// software grid barrier between steps. Block bid owns hidden cols
// j in [bid*8, bid*8+8) and gate columns {l*1024 + j} for l=0..3.
//
// Smem: Wt[1024][32] (W_hh rows for this block, K-major; 128 KB, loaded once)
//       bufs[8 warps][2][16*64]  h-staging double buffers (64 KB),
//       overlaid after GEMM as partials P[w][32n][64b].
// ---------------------------------------------------------------------------
__global__ __launch_bounds__(NTHR, 1) void lstm_persistent(
    const float* __restrict__ W_hh,
    float* __restrict__ ys,
    float* __restrict__ hout,
    float* __restrict__ cout)
{
    extern __shared__ float smem[];
    float* Wt   = smem;            // 32768 floats
    float* bufs = smem + 32768;    // 16384 floats

    const int tid  = threadIdx.x;
    const int wid  = tid >> 5;
    const int lane = tid & 31;
    const int bid  = blockIdx.x;
    const int j0   = bid * 8;

    // --- one-time: stage W_hh rows (transposed to [k][n]) ---
    for (int i = tid; i < 32 * 1024; i += NTHR) {
        int n = i >> 10, k = i & 1023;           // consecutive tid -> consecutive k (coalesced)
        int l = n >> 3, jj = n & 7;
        Wt[k * 32 + n] = W_hh[(size_t)(l * HID + j0 + jj) * HID + k];
    }

    const ull gen0 = *(volatile ull*)&g_bar_gen;
    __syncthreads();

    // GEMM lane mapping: 8b x 8n micro-tile, warp covers full 64x32 tile over K-slice 128
    const int b0 = (lane >> 2) * 8;     // batch base
    const int n0 = (lane & 3) * 8;      // gate-col base (of 32)
    const int kbase = wid * 128;        // warp K-slice
    float* buf0 = bufs + wid * 2048;
    float* buf1 = buf0 + 1024;

    // cell mapping: thread owns cells (cb, cjj) and (cb, cjj+1)
    const int cb  = tid >> 2;
    const int cjj = (tid & 3) * 2;
    float cst0 = 0.0f, cst1 = 0.0f;

    ull nbar = 0;

    for (int t = T_STEPS - 1; t >= 0; --t) {
        const bool first = (t == T_STEPS - 1);

        if (!first) {
            const float* h = ys + (size_t)(t + 1) * (BATCH * HID);
            const float* hp = h + kbase + (lane & 3) * 4 + (size_t)(lane >> 2) * HID;

            ull acc2[4][8];
#pragma unroll
            for (int p = 0; p < 4; p++)
#pragma unroll
                for (int n = 0; n < 8; n++) acc2[p][n] = 0ULL;

            // prologue: load chunk 0 (16 k x 64 b), store transposed into buf0
            float4 ld[8];
#pragma unroll
            for (int r = 0; r < 8; r++)
                ld[r] = *reinterpret_cast<const float4*>(hp + (size_t)r * 8 * HID);
            {
                const int bq = lane >> 2, kq = (lane & 3) * 4;
#pragma unroll
                for (int r = 0; r < 8; r++) {
                    int b = r * 8 + bq;
                    buf0[(kq + 0) * 64 + b] = ld[r].x;
                    buf0[(kq + 1) * 64 + b] = ld[r].y;
                    buf0[(kq + 2) * 64 + b] = ld[r].z;
                    buf0[(kq + 3) * 64 + b] = ld[r].w;
                }
            }
            __syncwarp();

            for (int ch = 0; ch < 8; ch++) {
                float* cur = (ch & 1) ? buf1 : buf0;
                if (ch < 7) {
#pragma unroll
                    for (int r = 0; r < 8; r++)
                        ld[r] = *reinterpret_cast<const float4*>(
                            hp + (ch + 1) * 16 + (size_t)r * 8 * HID);
                }
#pragma unroll
                for (int kk = 0; kk < 16; kk++) {
                    const int kg = kbase + ch * 16 + kk;
                    float4 a01 = *reinterpret_cast<const float4*>(&cur[kk * 64 + b0]);
                    float4 a23 = *reinterpret_cast<const float4*>(&cur[kk * 64 + b0 + 4]);
                    float4 w03 = *reinterpret_cast<const float4*>(&Wt[kg * 32 + n0]);
                    float4 w47 = *reinterpret_cast<const float4*>(&Wt[kg * 32 + n0 + 4]);
                    ull A[4] = {pk2(a01.x, a01.y), pk2(a01.z, a01.w),
                                pk2(a23.x, a23.y), pk2(a23.z, a23.w)};
                    ull W8[8] = {dup2(w03.x), dup2(w03.y), dup2(w03.z), dup2(w03.w),
                                 dup2(w47.x), dup2(w47.y), dup2(w47.z), dup2(w47.w)};
#pragma unroll
                    for (int p = 0; p < 4; p++)
#pragma unroll
                        for (int n = 0; n < 8; n++) fma2(acc2[p][n], A[p], W8[n]);
                }
                if (ch < 7) {
                    float* nxt = (ch & 1) ? buf0 : buf1;
                    __syncwarp();
                    const int bq = lane >> 2, kq = (lane & 3) * 4;
#pragma unroll
                    for (int r = 0; r < 8; r++) {
                        int b = r * 8 + bq;
                        nxt[(kq + 0) * 64 + b] = ld[r].x;
                        nxt[(kq + 1) * 64 + b] = ld[r].y;
                        nxt[(kq + 2) * 64 + b] = ld[r].z;
                        nxt[(kq + 3) * 64 + b] = ld[r].w;
                    }
                    __syncwarp();
                }
            }

            // write partials onto this warp's (now dead) staging buffers:
            // P[w][n][b], pairs contiguous in b
            __syncwarp();
            float* P = bufs + wid * 2048;
#pragma unroll
            for (int p = 0; p < 4; p++)
#pragma unroll
                for (int n = 0; n < 8; n++) {
                    float2 v = up2(acc2[p][n]);
                    *reinterpret_cast<float2*>(&P[(n0 + n) * 64 + b0 + 2 * p]) = v;
                }
        }
        __syncthreads();   // partials visible to all warps

        // ---- block-local LSTM cell for 2 cells/thread ----
        {
            const float* Gt = g_G + ((size_t)t * BATCH + cb) * GATES + j0;
            float gv0[4], gv1[4];
#pragma unroll
            for (int l = 0; l < 4; l++) {
                float sA = Gt[l * HID + cjj];
                float sB = Gt[l * HID + cjj + 1];
                if (!first) {
#pragma unroll
                    for (int w = 0; w < 8; w++) {
                        sA += bufs[w * 2048 + (l * 8 + cjj) * 64 + cb];
                        sB += bufs[w * 2048 + (l * 8 + cjj + 1) * 64 + cb];
                    }
                }
                gv0[l] = sA; gv1[l] = sB;
            }
            float i0 = sigf(gv0[0]), f0 = sigf(gv0[1]), gg0 = tanhf(gv0[2]), o0 = sigf(gv0[3]);
            float i1 = sigf(gv1[0]), f1 = sigf(gv1[1]), gg1 = tanhf(gv1[2]), o1 = sigf(gv1[3]);
            cst0 = first ? (i0 * gg0) : (f0 * cst0 + i0 * gg0);
            cst1 = first ? (i1 * gg1) : (f1 * cst1 + i1 * gg1);
            float h0 = o0 * tanhf(cst0);
            float h1 = o1 * tanhf(cst1);

            float2 hv = make_float2(h0, h1);
            *reinterpret_cast<float2*>(
                &ys[(size_t)t * (BATCH * HID) + (size_t)cb * HID + j0 + cjj]) = hv;
            if (t == 0) {
                *reinterpret_cast<float2*>(&hout[(size_t)cb * HID + j0 + cjj]) = hv;
                *reinterpret_cast<float2*>(&cout[(size_t)cb * HID + j0 + cjj]) =
                    make_float2(cst0, cst1);
            }
        }

        // ---- grid barrier (h of step t must be visible before step t-1 reads) ----
        if (t > 0) {
            __threadfence();
            __syncthreads();
            if (tid == 0) {
                nbar++;
                unsigned prev = atomicAdd(&g_bar_cnt, 1u);
                if (prev == (unsigned)(gridDim.x - 1)) {
                    atomicExch(&g_bar_cnt, 0u);
                    __threadfence();
                    atomicAdd(&g_bar_gen, 1ULL);
                } else {
                    while (*(volatile ull*)&g_bar_gen < gen0 + nbar) {
                        __nanosleep(32);
                    }
                }
                __threadfence();
            }
            __syncthreads();
        }
    }
}

// ---------------------------------------------------------------------------
extern "C" void kernel_launch(void* const* d_in, const int* in_sizes, int n_in,
                              void* d_out, int out_size)
{
    const float* x    = (const float*)d_in[0];
    const float* w_ih = (const float*)d_in[1];
    const float* w_hh = (const float*)d_in[2];
    const float* b_ih = (const float*)d_in[3];
    const float* b_hh = (const float*)d_in[4];

    float* out  = (float*)d_out;
    float* ys   = out;                                  // (T, B, H)
    float* hout = out + (size_t)T_STEPS * BATCH * HID;  // (1, B, H)
    float* cout = hout + (size_t)BATCH * HID;           // (1, B, H)

    const int smem_bytes = (32768 + 16384) * sizeof(float);  // 192 KB
    cudaFuncSetAttribute(lstm_persistent,
                         cudaFuncAttributeMaxDynamicSharedMemorySize, smem_bytes);

    // Node 1: all input projections (parallel over T)
    input_gemm_kernel<<<dim3(GATES / 128, (T_STEPS * BATCH) / 128), 256>>>(
        x, w_ih, b_ih, b_hh);

    // Node 2: entire reverse-time recurrence in one persistent kernel
    lstm_persistent<<<NBLK, NTHR, smem_bytes>>>(w_hh, ys, hout, cout);
}